// round 16
// baseline (speedup 1.0000x reference)
#include <cuda_runtime.h>
#include <cuda_bf16.h>
#include <cuda_fp16.h>
#include <math.h>
#include <stdint.h>

// ---------------- problem constants ----------------
#define BATCH   2
#define SEQ     2048
#define HID     2048
#define INTER   4096
#define HEADS   64
#define NSTATE  128
#define KCONV   4
#define GTS     128
#define CONV_DIM (INTER + 2*GTS)             // 4352
#define PROJ_DIM (2*INTER + 2*GTS + HEADS)   // 8512
#define ROWS    (BATCH*SEQ)                  // 4096
#define EPS     1e-5f
#define NPAD1   8576
#define NPAD2   2048

// ---------------- scratch ----------------
__device__ float g_proj[(size_t)ROWS * PROJ_DIM];
__device__ float g_xbc [(size_t)ROWS * CONV_DIM];
__device__ float g_dt  [(size_t)ROWS * HEADS];
__device__ float g_dA  [(size_t)ROWS * HEADS];
__device__ float g_y   [(size_t)ROWS * INTER];   // n-half 0 partial (+ D*x)
__device__ float g_y2  [(size_t)ROWS * INTER];   // n-half 1 partial

__device__ __half g_Ah [(size_t)ROWS  * HID];
__device__ __half g_Al [(size_t)ROWS  * HID];
__device__ __half g_B1 [(size_t)NPAD1 * HID];
__device__ __half g_B2 [(size_t)NPAD2 * INTER];
__device__ __half g_Yh [(size_t)ROWS  * INTER];
__device__ __half g_Yl [(size_t)ROWS  * INTER];

// ---------------- helpers ----------------
__device__ __forceinline__ uint32_t s2u(const void* p){
    uint32_t a;
    asm("{ .reg .u64 t; cvta.to.shared.u64 t, %1; cvt.u32.u64 %0, t; }" : "=r"(a) : "l"(p));
    return a;
}
__device__ __forceinline__ void cp16(uint32_t d, const void* s){
    asm volatile("cp.async.cg.shared.global [%0], [%1], 16;" :: "r"(d), "l"(s));
}
__device__ __forceinline__ void cp4(uint32_t d, const void* s){
    asm volatile("cp.async.ca.shared.global [%0], [%1], 4;" :: "r"(d), "l"(s));
}
__device__ __forceinline__ void ldsm4(uint32_t* r, uint32_t a){
    asm volatile("ldmatrix.sync.aligned.m8n8.x4.shared.b16 {%0,%1,%2,%3}, [%4];"
        : "=r"(r[0]), "=r"(r[1]), "=r"(r[2]), "=r"(r[3]) : "r"(a));
}
__device__ __forceinline__ void mma16816(float* d, const uint32_t* a, const uint32_t* b){
    asm volatile("mma.sync.aligned.m16n8k16.row.col.f32.f16.f16.f32 "
        "{%0,%1,%2,%3}, {%4,%5,%6,%7}, {%8,%9}, {%0,%1,%2,%3};"
        : "+f"(d[0]), "+f"(d[1]), "+f"(d[2]), "+f"(d[3])
        : "r"(a[0]), "r"(a[1]), "r"(a[2]), "r"(a[3]), "r"(b[0]), "r"(b[1]));
}
// f32x2 packed math
__device__ __forceinline__ unsigned long long pk2(float x, float y){
    unsigned long long r; asm("mov.b64 %0, {%1,%2};" : "=l"(r) : "f"(x), "f"(y)); return r;
}
__device__ __forceinline__ unsigned long long fma2_(unsigned long long a, unsigned long long b, unsigned long long c){
    unsigned long long d; asm("fma.rn.f32x2 %0, %1, %2, %3;" : "=l"(d) : "l"(a), "l"(b), "l"(c)); return d;
}
__device__ __forceinline__ unsigned long long mul2_(unsigned long long a, unsigned long long b){
    unsigned long long d; asm("mul.rn.f32x2 %0, %1, %2;" : "=l"(d) : "l"(a), "l"(b)); return d;
}
__device__ __forceinline__ unsigned long long add2_(unsigned long long a, unsigned long long b){
    unsigned long long d; asm("add.rn.f32x2 %0, %1, %2;" : "=l"(d) : "l"(a), "l"(b)); return d;
}

// ---------------- fp32 -> fp16 hi/lo split ----------------
__global__ void split_kernel(const float* __restrict__ src,
                             __half* __restrict__ hi,
                             __half* __restrict__ lo, size_t n4)
{
    size_t i = (size_t)blockIdx.x * blockDim.x + threadIdx.x;
    if (i >= n4) return;
    size_t idx = i * 4;
    float4 v = *(const float4*)(src + idx);
    __half h0 = __float2half(v.x), h1 = __float2half(v.y),
           h2 = __float2half(v.z), h3 = __float2half(v.w);
    __half l0 = __float2half(v.x - __half2float(h0));
    __half l1 = __float2half(v.y - __half2float(h1));
    __half l2 = __float2half(v.z - __half2float(h2));
    __half l3 = __float2half(v.w - __half2float(h3));
    hi[idx+0]=h0; hi[idx+1]=h1; hi[idx+2]=h2; hi[idx+3]=h3;
    lo[idx+0]=l0; lo[idx+1]=l1; lo[idx+2]=l2; lo[idx+3]=l3;
}

// transpose: W[K,N] -> out[Npad, K] single fp16
__global__ void splitT_kernel(const float* __restrict__ W,
                              __half* __restrict__ T,
                              int Kdim, int N)
{
    __shared__ float tile[32][33];
    int nb = blockIdx.x * 32, kb = blockIdx.y * 32;
    for (int i = threadIdx.y; i < 32; i += 8) {
        int k = kb + i, n = nb + threadIdx.x;
        tile[i][threadIdx.x] = (n < N) ? W[(size_t)k * N + n] : 0.f;
    }
    __syncthreads();
    for (int i = threadIdx.y; i < 32; i += 8) {
        int n = nb + i, k = kb + threadIdx.x;
        T[(size_t)n * Kdim + k] = __float2half(tile[threadIdx.x][i]);
    }
}

// ---------------- HMMA fp16 2-pass GEMM, 4-stage ring (round-14) ----------------
#define TILE_SWZ 8192
#define OFF_AH   0
#define OFF_AL   TILE_SWZ
#define OFF_B    (2 * TILE_SWZ)
#define STAGE_B  (3 * TILE_SWZ)  // 24576
#define GSMEM    (4 * STAGE_B)   // 98304

__device__ __forceinline__ void g_load_stage(uint32_t st,
    const __half* Ah, const __half* Al, const __half* B,
    int rowBase, int colBase, int K, int kbase, int tid)
{
#pragma unroll
    for (int j = 0; j < 4; j++) {
        int idx = tid + j * 128;
        int r = idx >> 2, cq = idx & 3;
        uint32_t so = (uint32_t)(r * 64 + ((cq * 16) ^ ((r & 6) << 3)));
        size_t ga = (size_t)(rowBase + r) * K + kbase + cq * 8;
        size_t gb = (size_t)(colBase + r) * K + kbase + cq * 8;
        cp16(st + OFF_AH + so, Ah + ga);
        cp16(st + OFF_AL + so, Al + ga);
        cp16(st + OFF_B  + so, B  + gb);
    }
}

__global__ __launch_bounds__(128, 2)
void gemm2p_kernel(const __half* __restrict__ Ah, const __half* __restrict__ Al,
                   const __half* __restrict__ B,
                   float* __restrict__ C, int K, int Nvalid, int mode)
{
    extern __shared__ __align__(16) char smem[];
    const int tid  = threadIdx.x;
    const int wid  = tid >> 5;
    const int lane = tid & 31;
    const uint32_t sb = s2u(smem);
    const int rowBase = blockIdx.y * 128;
    const int colBase = blockIdx.x * 128;
    const int mbase = (wid & 1) * 64;
    const int nbase = (wid >> 1) * 64;

    float acc[4][8][4];
#pragma unroll
    for (int i = 0; i < 4; i++)
#pragma unroll
        for (int j = 0; j < 8; j++)
#pragma unroll
            for (int q = 0; q < 4; q++) acc[i][j][q] = 0.f;

    const int nch = K / 32;

    g_load_stage(sb,               Ah, Al, B, rowBase, colBase, K, 0,  tid);
    asm volatile("cp.async.commit_group;");
    g_load_stage(sb + STAGE_B,     Ah, Al, B, rowBase, colBase, K, 32, tid);
    asm volatile("cp.async.commit_group;");
    g_load_stage(sb + 2 * STAGE_B, Ah, Al, B, rowBase, colBase, K, 64, tid);
    asm volatile("cp.async.commit_group;");

    const uint32_t xorv = (uint32_t)((lane & 6) << 3);
    const uint32_t aRow = (uint32_t)(lane & 15);
    const uint32_t aCol0 = (uint32_t)((lane >> 4) * 16);
    const uint32_t bRow = (uint32_t)((lane & 7) + ((lane >> 4) & 1) * 8);
    const uint32_t bCol0 = (uint32_t)(((lane >> 3) & 1) * 16);

    uint32_t aC[2], bC[2];
#pragma unroll
    for (int ks = 0; ks < 2; ks++) {
        aC[ks] = (aCol0 + ks * 32) ^ xorv;
        bC[ks] = (bCol0 + ks * 32) ^ xorv;
    }

    for (int c = 0; c < nch; c++) {
        asm volatile("cp.async.wait_group 2;" ::: "memory");
        __syncthreads();

        if (c + 3 < nch) {
            uint32_t stp = sb + ((c + 3) & 3) * STAGE_B;
            g_load_stage(stp, Ah, Al, B, rowBase, colBase, K, (c + 3) * 32, tid);
        }
        asm volatile("cp.async.commit_group;");

        const uint32_t st  = sb + (c & 3) * STAGE_B;
        const uint32_t uAh = st + OFF_AH + (uint32_t)(mbase + aRow) * 64;
        const uint32_t uAl = st + OFF_AL + (uint32_t)(mbase + aRow) * 64;
        const uint32_t uB  = st + OFF_B  + (uint32_t)(nbase + bRow) * 64;

#pragma unroll
        for (int ks = 0; ks < 2; ks++) {
            uint32_t ah[4][4], xb[4][4];
#pragma unroll
            for (int mi = 0; mi < 4; mi++) ldsm4(ah[mi], uAh + mi * (16*64) + aC[ks]);
#pragma unroll
            for (int nj = 0; nj < 4; nj++) ldsm4(xb[nj], uB + nj * (16*64) + bC[ks]);
#pragma unroll
            for (int mi = 0; mi < 4; mi++)
#pragma unroll
                for (int nj = 0; nj < 4; nj++) {
                    mma16816(acc[mi][2*nj],   ah[mi], &xb[nj][0]);
                    mma16816(acc[mi][2*nj+1], ah[mi], &xb[nj][2]);
                }
#pragma unroll
            for (int mi = 0; mi < 4; mi++) ldsm4(ah[mi], uAl + mi * (16*64) + aC[ks]);
#pragma unroll
            for (int mi = 0; mi < 4; mi++)
#pragma unroll
                for (int nj = 0; nj < 4; nj++) {
                    mma16816(acc[mi][2*nj],   ah[mi], &xb[nj][0]);
                    mma16816(acc[mi][2*nj+1], ah[mi], &xb[nj][2]);
                }
        }
    }

    // epilogue
#pragma unroll
    for (int mi = 0; mi < 4; mi++) {
        int row0 = rowBase + mbase + mi * 16 + (lane >> 2);
#pragma unroll
        for (int nj = 0; nj < 8; nj++) {
            int col = colBase + nbase + nj * 8 + (lane & 3) * 2;
            if (col < Nvalid) {
                float s = 1.0f;
                if (mode) s = (col < INTER) ? 0.25f : (col < INTER + CONV_DIM) ? 0.5f : 1.0f;
                float2 v0 = make_float2(acc[mi][nj][0] * s, acc[mi][nj][1] * s);
                float2 v1 = make_float2(acc[mi][nj][2] * s, acc[mi][nj][3] * s);
                *(float2*)(C + (size_t)row0 * Nvalid + col)       = v0;
                *(float2*)(C + (size_t)(row0 + 8) * Nvalid + col) = v1;
            }
        }
    }
}

// ---------------- fused depthwise conv + SiLU + dt/dA ----------------
#define T_CHUNK 128
#define FCOLS (CONV_DIM + HEADS)   // 4416
__global__ void conv_silu_dt_kernel(const float* __restrict__ proj,
                                    const float* __restrict__ cw,
                                    const float* __restrict__ cb,
                                    const float* __restrict__ dt_bias,
                                    const float* __restrict__ A_log,
                                    float* __restrict__ xbc,
                                    float* __restrict__ dts,
                                    float* __restrict__ dAs)
{
    int c = blockIdx.x * blockDim.x + threadIdx.x;
    if (c >= FCOLS) return;
    int bz = blockIdx.y;
    int b  = bz / (SEQ / T_CHUNK);
    int t0 = (bz % (SEQ / T_CHUNK)) * T_CHUNK;
    const float* pcol = proj + INTER + c;

    if (c < CONV_DIM) {
        float w0 = cw[c*KCONV+0], w1 = cw[c*KCONV+1], w2 = cw[c*KCONV+2], w3 = cw[c*KCONV+3];
        float bias = cb[c];
        float x0 = (t0 >= 3) ? pcol[(size_t)(b*SEQ + t0 - 3) * PROJ_DIM] : 0.f;
        float x1 = (t0 >= 2) ? pcol[(size_t)(b*SEQ + t0 - 2) * PROJ_DIM] : 0.f;
        float x2 = (t0 >= 1) ? pcol[(size_t)(b*SEQ + t0 - 1) * PROJ_DIM] : 0.f;
        for (int t = t0; t < t0 + T_CHUNK; t++) {
            float x3 = pcol[(size_t)(b*SEQ + t) * PROJ_DIM];
            float v  = bias + w0*x0 + w1*x1 + w2*x2 + w3*x3;
            float s  = v / (1.f + __expf(-v));
            xbc[(size_t)(b*SEQ + t) * CONV_DIM + c] = s;
            x0 = x1; x1 = x2; x2 = x3;
        }
    } else {
        int h = c - CONV_DIM;
        float bias = dt_bias[h];
        float A = -expf(A_log[h]);
        for (int t = t0; t < t0 + T_CHUNK; t++) {
            float d  = pcol[(size_t)(b*SEQ + t) * PROJ_DIM] + bias;
            float sp = (d > 20.f) ? d : log1pf(expf(d));
            size_t o = (size_t)(b*SEQ + t) * HEADS + h;
            dts[o] = sp;
            dAs[o] = expf(sp * A);
        }
    }
}

// ---------------- selective scan: p-split x n-split, TB=16 ----------------
// 512 CTAs: blockIdx.x = b*256 + h*4 + quarter; phalf = quarter&1, nhalf = quarter>>1.
// 128 threads: pl = tid>>2 (0..31), nc = tid&3 (16 n's each -> 64 n per CTA).
// Writes partial y to g_y (nhalf 0, + D*x) / g_y2 (nhalf 1); summed in norm_gate.
#define TB    16
#define NBLK  (SEQ / TB)   // 128

__device__ __forceinline__ void scan_load_block(
    uint32_t uBC, uint32_t uX, uint32_t uM,
    const float* base0, const float* dts, const float* dAs,
    int bSEQ, int h, int phalf, int nhalf, int blk, int buf, int tid)
{
    const int t0 = blk * TB;
    const float* bb = base0 + (size_t)t0 * CONV_DIM;
    // BC: TB steps * 128 floats (64 B + 64 C) = 512 x 16B slots -> 4 iters
#pragma unroll
    for (int i = 0; i < 4; i++) {
        int slot = tid + i * 128;
        int s = slot >> 5, w = slot & 31;   // w: 0..15 B part, 16..31 C part
        size_t gcol = (w < 16) ? (size_t)(INTER + nhalf * 64 + w * 4)
                               : (size_t)(INTER + 128 + nhalf * 64 + (w - 16) * 4);
        cp16(uBC + (uint32_t)(buf * (TB*512) + s * 512 + w * 16),
             bb + (size_t)s * CONV_DIM + gcol);
    }
    // x: TB*32 floats = 128 x 16B slots
    {
        int s = tid >> 3, w = tid & 7;
        cp16(uX + (uint32_t)(buf * (TB*128) + s * 128 + w * 16),
             bb + (size_t)s * CONV_DIM + h * 64 + phalf * 32 + w * 4);
    }
    if (tid < TB) {
        cp4(uM + (uint32_t)(buf * (TB*16) + tid * 16),
            dts + (size_t)(bSEQ + t0 + tid) * HEADS + h);
    } else if (tid < 2*TB) {
        int s = tid - TB;
        cp4(uM + (uint32_t)(buf * (TB*16) + s * 16 + 4),
            dAs + (size_t)(bSEQ + t0 + s) * HEADS + h);
    }
}

__global__ __launch_bounds__(128, 3)
void scan_kernel(const float* __restrict__ xbc,
                 const float* __restrict__ dts,
                 const float* __restrict__ dAs,
                 const float* __restrict__ Dv,
                 float* __restrict__ y1,
                 float* __restrict__ y2)
{
    const int bi    = blockIdx.x;
    const int phalf = bi & 1;
    const int nhalf = (bi >> 1) & 1;
    const int h     = (bi >> 2) & 63;
    const int b     = bi >> 8;
    const int tid   = threadIdx.x;
    const int pl    = tid >> 2;
    const int nc    = tid & 3;

    __shared__ __align__(16) float sBC[2][TB][128];               // 16 KB
    __shared__ __align__(16) float sx [2][TB][32];                // 4 KB
    __shared__ __align__(16) float sMeta[2][TB][4];               // 512 B
    __shared__ __align__(16) unsigned long long sAcc[TB][32][4];  // 16 KB

    const uint32_t uBC = s2u(sBC);
    const uint32_t uX  = s2u(sx);
    const uint32_t uM  = s2u(sMeta);

    unsigned long long st[8];
#pragma unroll
    for (int j = 0; j < 8; j++) st[j] = 0ull;

    const float Dh = Dv[h];
    const int bSEQ = b * SEQ;
    const float* base0 = xbc + (size_t)bSEQ * CONV_DIM;
    float* ybase = (nhalf ? y2 : y1) + (size_t)bSEQ * INTER + h * 64 + phalf * 32;

    scan_load_block(uBC, uX, uM, base0, dts, dAs, bSEQ, h, phalf, nhalf, 0, 0, tid);
    asm volatile("cp.async.commit_group;");

    for (int blk = 0; blk < NBLK; blk++) {
        const int buf = blk & 1;
        asm volatile("cp.async.wait_group 0;" ::: "memory");
        __syncthreads();

        if (blk + 1 < NBLK) {
            scan_load_block(uBC, uX, uM, base0, dts, dAs, bSEQ, h, phalf, nhalf,
                            blk + 1, buf ^ 1, tid);
            asm volatile("cp.async.commit_group;");
        }

#pragma unroll
        for (int s = 0; s < TB; s++) {
            const float dt  = sMeta[buf][s][0];
            const float dA  = sMeta[buf][s][1];
            const float xp  = sx[buf][s][pl];
            const float dtx = dt * xp;
            const unsigned long long dA2  = pk2(dA, dA);
            const unsigned long long dtx2 = pk2(dtx, dtx);

            const char* rowB = (const char*)&sBC[buf][s][0];
            const char* rowC = rowB + 256;

            unsigned long long a0 = 0ull, a1 = 0ull, a2 = 0ull, a3 = 0ull;
#pragma unroll
            for (int q = 0; q < 4; q += 2) {
                const uint32_t o0 = (uint32_t)((q * 4 + nc) * 16);
                const uint32_t o1 = (uint32_t)(((q + 1) * 4 + nc) * 16);
                ulonglong2 bq0 = *(const ulonglong2*)(rowB + o0);
                ulonglong2 cq0 = *(const ulonglong2*)(rowC + o0);
                ulonglong2 bq1 = *(const ulonglong2*)(rowB + o1);
                ulonglong2 cq1 = *(const ulonglong2*)(rowC + o1);
                st[2*q]   = fma2_(st[2*q],   dA2, mul2_(dtx2, bq0.x));
                a0 = fma2_(cq0.x, st[2*q],   a0);
                st[2*q+1] = fma2_(st[2*q+1], dA2, mul2_(dtx2, bq0.y));
                a1 = fma2_(cq0.y, st[2*q+1], a1);
                st[2*q+2] = fma2_(st[2*q+2], dA2, mul2_(dtx2, bq1.x));
                a2 = fma2_(cq1.x, st[2*q+2], a2);
                st[2*q+3] = fma2_(st[2*q+3], dA2, mul2_(dtx2, bq1.y));
                a3 = fma2_(cq1.y, st[2*q+3], a3);
            }
            a0 = add2_(a0, a1);
            a2 = add2_(a2, a3);
            sAcc[s][pl][nc] = add2_(a0, a2);
        }
        __syncthreads();

        const int t0 = blk * TB;
#pragma unroll
        for (int i = 0; i < 4; i++) {
            int idx = tid + i * 128;
            int s  = idx >> 5;
            int pp = idx & 31;
            ulonglong2 v0 = *(const ulonglong2*)&sAcc[s][pp][0];
            ulonglong2 v1 = *(const ulonglong2*)&sAcc[s][pp][2];
            unsigned long long t = add2_(add2_(v0.x, v0.y), add2_(v1.x, v1.y));
            float f0, f1;
            asm("mov.b64 {%0,%1}, %2;" : "=f"(f0), "=f"(f1) : "l"(t));
            float r = f0 + f1;
            if (nhalf == 0) r += Dh * sx[buf][s][pp];
            ybase[(size_t)(t0 + s) * INTER + pp] = r;
        }
    }
}

// ---------------- RMS norm + SiLU gate + fp16 hi/lo split (sums partials) ----
__global__ void norm_gate_kernel(const float* __restrict__ y1,
                                 const float* __restrict__ y2,
                                 const float* __restrict__ proj,
                                 const float* __restrict__ norm_w,
                                 __half* __restrict__ Yh,
                                 __half* __restrict__ Yl)
{
    const int row = blockIdx.x;
    const int tid = threadIdx.x;
    __shared__ float red[8];
    __shared__ float s_scale;

    float s = 0.f;
    for (int i = tid; i < INTER; i += 256) {
        float v = y1[(size_t)row * INTER + i] + y2[(size_t)row * INTER + i];
        s += v * v;
    }
#pragma unroll
    for (int o = 16; o > 0; o >>= 1) s += __shfl_xor_sync(0xffffffffu, s, o);
    if ((tid & 31) == 0) red[tid >> 5] = s;
    __syncthreads();
    if (tid == 0) {
        float tot = 0.f;
#pragma unroll
        for (int w = 0; w < 8; w++) tot += red[w];
        s_scale = rsqrtf(tot / (float)INTER + EPS);
    }
    __syncthreads();
    const float scale = s_scale;

    for (int i = tid; i < INTER; i += 256) {
        float v  = y1[(size_t)row * INTER + i] + y2[(size_t)row * INTER + i];
        float zz = proj[(size_t)row * PROJ_DIM + i];
        float g  = zz / (1.f + __expf(-zz));
        float r  = v * scale * norm_w[i] * g;
        __half hh = __float2half(r);
        __half ll = __float2half(r - __half2float(hh));
        Yh[(size_t)row * INTER + i] = hh;
        Yl[(size_t)row * INTER + i] = ll;
    }
}

// ---------------- launch ----------------
extern "C" void kernel_launch(void* const* d_in, const int* in_sizes, int n_in,
                              void* d_out, int out_size)
{
    const float* hidden    = (const float*)d_in[0];
    const float* in_proj_w = (const float*)d_in[1];
    const float* conv_w    = (const float*)d_in[2];
    const float* conv_b    = (const float*)d_in[3];
    const float* A_log     = (const float*)d_in[4];
    const float* Dv        = (const float*)d_in[5];
    const float* dt_bias   = (const float*)d_in[6];
    const float* norm_w    = (const float*)d_in[7];
    const float* out_proj_w= (const float*)d_in[8];
    float* out = (float*)d_out;

    float *p_proj, *p_xbc, *p_dt, *p_dA, *p_y, *p_y2;
    __half *p_Ah, *p_Al, *p_B1, *p_B2, *p_Yh, *p_Yl;
    cudaGetSymbolAddress((void**)&p_proj, g_proj);
    cudaGetSymbolAddress((void**)&p_xbc,  g_xbc);
    cudaGetSymbolAddress((void**)&p_dt,   g_dt);
    cudaGetSymbolAddress((void**)&p_dA,   g_dA);
    cudaGetSymbolAddress((void**)&p_y,    g_y);
    cudaGetSymbolAddress((void**)&p_y2,   g_y2);
    cudaGetSymbolAddress((void**)&p_Ah,   g_Ah);
    cudaGetSymbolAddress((void**)&p_Al,   g_Al);
    cudaGetSymbolAddress((void**)&p_B1,   g_B1);
    cudaGetSymbolAddress((void**)&p_B2,   g_B2);
    cudaGetSymbolAddress((void**)&p_Yh,   g_Yh);
    cudaGetSymbolAddress((void**)&p_Yl,   g_Yl);

    cudaFuncSetAttribute(gemm2p_kernel, cudaFuncAttributeMaxDynamicSharedMemorySize, GSMEM);

    // conversions
    {
        size_t n4 = (size_t)ROWS * HID / 4;
        split_kernel<<<(unsigned)((n4 + 255) / 256), 256>>>(hidden, p_Ah, p_Al, n4);
    }
    {
        dim3 grid(NPAD1 / 32, HID / 32);
        splitT_kernel<<<grid, dim3(32, 8)>>>(in_proj_w, p_B1, HID, PROJ_DIM);
    }
    {
        dim3 grid(NPAD2 / 32, INTER / 32);
        splitT_kernel<<<grid, dim3(32, 8)>>>(out_proj_w, p_B2, INTER, HID);
    }

    // GEMM1: proj = hidden @ in_proj_w * mup
    {
        dim3 grid(NPAD1 / 128, ROWS / 128);
        gemm2p_kernel<<<grid, 128, GSMEM>>>(p_Ah, p_Al, p_B1, p_proj,
                                            HID, PROJ_DIM, 1);
    }

    // fused conv + silu + dt/dA
    {
        dim3 grid((FCOLS + 127) / 128, BATCH * (SEQ / T_CHUNK));
        conv_silu_dt_kernel<<<grid, 128>>>(p_proj, conv_w, conv_b,
                                           dt_bias, A_log,
                                           p_xbc, p_dt, p_dA);
    }

    // scan (p-split x n-split: 4 CTAs per (b,h))
    scan_kernel<<<BATCH * HEADS * 4, 128>>>(p_xbc, p_dt, p_dA, Dv, p_y, p_y2);

    // norm + gate + split (sums the two n-half partials)
    norm_gate_kernel<<<ROWS, 256>>>(p_y, p_y2, p_proj, norm_w, p_Yh, p_Yl);

    // GEMM2: out = gated @ out_proj_w
    {
        dim3 grid(NPAD2 / 128, ROWS / 128);
        gemm2p_kernel<<<grid, 128, GSMEM>>>(p_Yh, p_Yl, p_B2, out,
                                            INTER, HID, 0);
    }
    (void)in_sizes; (void)n_in; (void)out_size;
}

// round 17
// speedup vs baseline: 1.0840x; 1.0840x over previous
#include <cuda_runtime.h>
#include <cuda_bf16.h>
#include <cuda_fp16.h>
#include <math.h>
#include <stdint.h>

// ---------------- problem constants ----------------
#define BATCH   2
#define SEQ     2048
#define HID     2048
#define INTER   4096
#define HEADS   64
#define NSTATE  128
#define KCONV   4
#define GTS     128
#define CONV_DIM (INTER + 2*GTS)             // 4352
#define PROJ_DIM (2*INTER + 2*GTS + HEADS)   // 8512
#define ROWS    (BATCH*SEQ)                  // 4096
#define EPS     1e-5f
#define NPAD1   8576
#define NPAD2   2048

// ---------------- scratch ----------------
__device__ float g_proj[(size_t)ROWS * PROJ_DIM];
__device__ float g_xbc [(size_t)ROWS * CONV_DIM];
__device__ float g_dt  [(size_t)ROWS * HEADS];
__device__ float g_dA  [(size_t)ROWS * HEADS];
__device__ float g_y   [(size_t)ROWS * INTER];

__device__ __half g_Ah [(size_t)ROWS  * HID];
__device__ __half g_Al [(size_t)ROWS  * HID];
__device__ __half g_B1 [(size_t)NPAD1 * HID];
__device__ __half g_B2 [(size_t)NPAD2 * INTER];
__device__ __half g_Yh [(size_t)ROWS  * INTER];
__device__ __half g_Yl [(size_t)ROWS  * INTER];

// ---------------- helpers ----------------
__device__ __forceinline__ uint32_t s2u(const void* p){
    uint32_t a;
    asm("{ .reg .u64 t; cvta.to.shared.u64 t, %1; cvt.u32.u64 %0, t; }" : "=r"(a) : "l"(p));
    return a;
}
__device__ __forceinline__ void cp16(uint32_t d, const void* s){
    asm volatile("cp.async.cg.shared.global [%0], [%1], 16;" :: "r"(d), "l"(s));
}
__device__ __forceinline__ void cp4(uint32_t d, const void* s){
    asm volatile("cp.async.ca.shared.global [%0], [%1], 4;" :: "r"(d), "l"(s));
}
__device__ __forceinline__ void ldsm4(uint32_t* r, uint32_t a){
    asm volatile("ldmatrix.sync.aligned.m8n8.x4.shared.b16 {%0,%1,%2,%3}, [%4];"
        : "=r"(r[0]), "=r"(r[1]), "=r"(r[2]), "=r"(r[3]) : "r"(a));
}
__device__ __forceinline__ void mma16816(float* d, const uint32_t* a, const uint32_t* b){
    asm volatile("mma.sync.aligned.m16n8k16.row.col.f32.f16.f16.f32 "
        "{%0,%1,%2,%3}, {%4,%5,%6,%7}, {%8,%9}, {%0,%1,%2,%3};"
        : "+f"(d[0]), "+f"(d[1]), "+f"(d[2]), "+f"(d[3])
        : "r"(a[0]), "r"(a[1]), "r"(a[2]), "r"(a[3]), "r"(b[0]), "r"(b[1]));
}
// f32x2 packed math
__device__ __forceinline__ unsigned long long pk2(float x, float y){
    unsigned long long r; asm("mov.b64 %0, {%1,%2};" : "=l"(r) : "f"(x), "f"(y)); return r;
}
__device__ __forceinline__ unsigned long long fma2_(unsigned long long a, unsigned long long b, unsigned long long c){
    unsigned long long d; asm("fma.rn.f32x2 %0, %1, %2, %3;" : "=l"(d) : "l"(a), "l"(b), "l"(c)); return d;
}
__device__ __forceinline__ unsigned long long mul2_(unsigned long long a, unsigned long long b){
    unsigned long long d; asm("mul.rn.f32x2 %0, %1, %2;" : "=l"(d) : "l"(a), "l"(b)); return d;
}
__device__ __forceinline__ unsigned long long add2_(unsigned long long a, unsigned long long b){
    unsigned long long d; asm("add.rn.f32x2 %0, %1, %2;" : "=l"(d) : "l"(a), "l"(b)); return d;
}

// ---------------- fp32 -> fp16 hi/lo split ----------------
__global__ void split_kernel(const float* __restrict__ src,
                             __half* __restrict__ hi,
                             __half* __restrict__ lo, size_t n4)
{
    size_t i = (size_t)blockIdx.x * blockDim.x + threadIdx.x;
    if (i >= n4) return;
    size_t idx = i * 4;
    float4 v = *(const float4*)(src + idx);
    __half h0 = __float2half(v.x), h1 = __float2half(v.y),
           h2 = __float2half(v.z), h3 = __float2half(v.w);
    __half l0 = __float2half(v.x - __half2float(h0));
    __half l1 = __float2half(v.y - __half2float(h1));
    __half l2 = __float2half(v.z - __half2float(h2));
    __half l3 = __float2half(v.w - __half2float(h3));
    hi[idx+0]=h0; hi[idx+1]=h1; hi[idx+2]=h2; hi[idx+3]=h3;
    lo[idx+0]=l0; lo[idx+1]=l1; lo[idx+2]=l2; lo[idx+3]=l3;
}

// transpose: W[K,N] -> out[Npad, K] single fp16
__global__ void splitT_kernel(const float* __restrict__ W,
                              __half* __restrict__ T,
                              int Kdim, int N)
{
    __shared__ float tile[32][33];
    int nb = blockIdx.x * 32, kb = blockIdx.y * 32;
    for (int i = threadIdx.y; i < 32; i += 8) {
        int k = kb + i, n = nb + threadIdx.x;
        tile[i][threadIdx.x] = (n < N) ? W[(size_t)k * N + n] : 0.f;
    }
    __syncthreads();
    for (int i = threadIdx.y; i < 32; i += 8) {
        int n = nb + i, k = kb + threadIdx.x;
        T[(size_t)n * Kdim + k] = __float2half(tile[threadIdx.x][i]);
    }
}

// ---------------- HMMA fp16 2-pass GEMM, 4-stage ring (round-14) ----------------
#define TILE_SWZ 8192
#define OFF_AH   0
#define OFF_AL   TILE_SWZ
#define OFF_B    (2 * TILE_SWZ)
#define STAGE_B  (3 * TILE_SWZ)  // 24576
#define GSMEM    (4 * STAGE_B)   // 98304

__device__ __forceinline__ void g_load_stage(uint32_t st,
    const __half* Ah, const __half* Al, const __half* B,
    int rowBase, int colBase, int K, int kbase, int tid)
{
#pragma unroll
    for (int j = 0; j < 4; j++) {
        int idx = tid + j * 128;
        int r = idx >> 2, cq = idx & 3;
        uint32_t so = (uint32_t)(r * 64 + ((cq * 16) ^ ((r & 6) << 3)));
        size_t ga = (size_t)(rowBase + r) * K + kbase + cq * 8;
        size_t gb = (size_t)(colBase + r) * K + kbase + cq * 8;
        cp16(st + OFF_AH + so, Ah + ga);
        cp16(st + OFF_AL + so, Al + ga);
        cp16(st + OFF_B  + so, B  + gb);
    }
}

__global__ __launch_bounds__(128, 2)
void gemm2p_kernel(const __half* __restrict__ Ah, const __half* __restrict__ Al,
                   const __half* __restrict__ B,
                   float* __restrict__ C, int K, int Nvalid, int mode)
{
    extern __shared__ __align__(16) char smem[];
    const int tid  = threadIdx.x;
    const int wid  = tid >> 5;
    const int lane = tid & 31;
    const uint32_t sb = s2u(smem);
    const int rowBase = blockIdx.y * 128;
    const int colBase = blockIdx.x * 128;
    const int mbase = (wid & 1) * 64;
    const int nbase = (wid >> 1) * 64;

    float acc[4][8][4];
#pragma unroll
    for (int i = 0; i < 4; i++)
#pragma unroll
        for (int j = 0; j < 8; j++)
#pragma unroll
            for (int q = 0; q < 4; q++) acc[i][j][q] = 0.f;

    const int nch = K / 32;

    g_load_stage(sb,               Ah, Al, B, rowBase, colBase, K, 0,  tid);
    asm volatile("cp.async.commit_group;");
    g_load_stage(sb + STAGE_B,     Ah, Al, B, rowBase, colBase, K, 32, tid);
    asm volatile("cp.async.commit_group;");
    g_load_stage(sb + 2 * STAGE_B, Ah, Al, B, rowBase, colBase, K, 64, tid);
    asm volatile("cp.async.commit_group;");

    const uint32_t xorv = (uint32_t)((lane & 6) << 3);
    const uint32_t aRow = (uint32_t)(lane & 15);
    const uint32_t aCol0 = (uint32_t)((lane >> 4) * 16);
    const uint32_t bRow = (uint32_t)((lane & 7) + ((lane >> 4) & 1) * 8);
    const uint32_t bCol0 = (uint32_t)(((lane >> 3) & 1) * 16);

    uint32_t aC[2], bC[2];
#pragma unroll
    for (int ks = 0; ks < 2; ks++) {
        aC[ks] = (aCol0 + ks * 32) ^ xorv;
        bC[ks] = (bCol0 + ks * 32) ^ xorv;
    }

    for (int c = 0; c < nch; c++) {
        asm volatile("cp.async.wait_group 2;" ::: "memory");
        __syncthreads();

        if (c + 3 < nch) {
            uint32_t stp = sb + ((c + 3) & 3) * STAGE_B;
            g_load_stage(stp, Ah, Al, B, rowBase, colBase, K, (c + 3) * 32, tid);
        }
        asm volatile("cp.async.commit_group;");

        const uint32_t st  = sb + (c & 3) * STAGE_B;
        const uint32_t uAh = st + OFF_AH + (uint32_t)(mbase + aRow) * 64;
        const uint32_t uAl = st + OFF_AL + (uint32_t)(mbase + aRow) * 64;
        const uint32_t uB  = st + OFF_B  + (uint32_t)(nbase + bRow) * 64;

#pragma unroll
        for (int ks = 0; ks < 2; ks++) {
            uint32_t ah[4][4], xb[4][4];
#pragma unroll
            for (int mi = 0; mi < 4; mi++) ldsm4(ah[mi], uAh + mi * (16*64) + aC[ks]);
#pragma unroll
            for (int nj = 0; nj < 4; nj++) ldsm4(xb[nj], uB + nj * (16*64) + bC[ks]);
#pragma unroll
            for (int mi = 0; mi < 4; mi++)
#pragma unroll
                for (int nj = 0; nj < 4; nj++) {
                    mma16816(acc[mi][2*nj],   ah[mi], &xb[nj][0]);
                    mma16816(acc[mi][2*nj+1], ah[mi], &xb[nj][2]);
                }
#pragma unroll
            for (int mi = 0; mi < 4; mi++) ldsm4(ah[mi], uAl + mi * (16*64) + aC[ks]);
#pragma unroll
            for (int mi = 0; mi < 4; mi++)
#pragma unroll
                for (int nj = 0; nj < 4; nj++) {
                    mma16816(acc[mi][2*nj],   ah[mi], &xb[nj][0]);
                    mma16816(acc[mi][2*nj+1], ah[mi], &xb[nj][2]);
                }
        }
    }

    // epilogue
#pragma unroll
    for (int mi = 0; mi < 4; mi++) {
        int row0 = rowBase + mbase + mi * 16 + (lane >> 2);
#pragma unroll
        for (int nj = 0; nj < 8; nj++) {
            int col = colBase + nbase + nj * 8 + (lane & 3) * 2;
            if (col < Nvalid) {
                float s = 1.0f;
                if (mode) s = (col < INTER) ? 0.25f : (col < INTER + CONV_DIM) ? 0.5f : 1.0f;
                float2 v0 = make_float2(acc[mi][nj][0] * s, acc[mi][nj][1] * s);
                float2 v1 = make_float2(acc[mi][nj][2] * s, acc[mi][nj][3] * s);
                *(float2*)(C + (size_t)row0 * Nvalid + col)       = v0;
                *(float2*)(C + (size_t)(row0 + 8) * Nvalid + col) = v1;
            }
        }
    }
}

// ---------------- fused depthwise conv + SiLU + dt/dA ----------------
#define T_CHUNK 128
#define FCOLS (CONV_DIM + HEADS)   // 4416
__global__ void conv_silu_dt_kernel(const float* __restrict__ proj,
                                    const float* __restrict__ cw,
                                    const float* __restrict__ cb,
                                    const float* __restrict__ dt_bias,
                                    const float* __restrict__ A_log,
                                    float* __restrict__ xbc,
                                    float* __restrict__ dts,
                                    float* __restrict__ dAs)
{
    int c = blockIdx.x * blockDim.x + threadIdx.x;
    if (c >= FCOLS) return;
    int bz = blockIdx.y;
    int b  = bz / (SEQ / T_CHUNK);
    int t0 = (bz % (SEQ / T_CHUNK)) * T_CHUNK;
    const float* pcol = proj + INTER + c;

    if (c < CONV_DIM) {
        float w0 = cw[c*KCONV+0], w1 = cw[c*KCONV+1], w2 = cw[c*KCONV+2], w3 = cw[c*KCONV+3];
        float bias = cb[c];
        float x0 = (t0 >= 3) ? pcol[(size_t)(b*SEQ + t0 - 3) * PROJ_DIM] : 0.f;
        float x1 = (t0 >= 2) ? pcol[(size_t)(b*SEQ + t0 - 2) * PROJ_DIM] : 0.f;
        float x2 = (t0 >= 1) ? pcol[(size_t)(b*SEQ + t0 - 1) * PROJ_DIM] : 0.f;
        for (int t = t0; t < t0 + T_CHUNK; t++) {
            float x3 = pcol[(size_t)(b*SEQ + t) * PROJ_DIM];
            float v  = bias + w0*x0 + w1*x1 + w2*x2 + w3*x3;
            float s  = v / (1.f + __expf(-v));
            xbc[(size_t)(b*SEQ + t) * CONV_DIM + c] = s;
            x0 = x1; x1 = x2; x2 = x3;
        }
    } else {
        int h = c - CONV_DIM;
        float bias = dt_bias[h];
        float A = -expf(A_log[h]);
        for (int t = t0; t < t0 + T_CHUNK; t++) {
            float d  = pcol[(size_t)(b*SEQ + t) * PROJ_DIM] + bias;
            float sp = (d > 20.f) ? d : log1pf(expf(d));
            size_t o = (size_t)(b*SEQ + t) * HEADS + h;
            dts[o] = sp;
            dAs[o] = expf(sp * A);
        }
    }
}

// ---------------- selective scan: race-free TB=16 double-buffer (round-15) ----
#define TB    16
#define NBLK  (SEQ / TB)   // 128

__device__ __forceinline__ void scan_load_block(
    uint32_t uBC, uint32_t uX, uint32_t uM,
    const float* base0, const float* dts, const float* dAs,
    int bSEQ, int h, int half, int blk, int buf, int tid)
{
    const int t0 = blk * TB;
    const float* bb = base0 + (size_t)t0 * CONV_DIM;
#pragma unroll
    for (int i = 0; i < 8; i++) {
        int slot = tid + i * 128;
        int s = slot >> 6, w = slot & 63;
        cp16(uBC + (uint32_t)(buf * (TB*1024) + s * 1024 + w * 16),
             bb + (size_t)s * CONV_DIM + INTER + w * 4);
    }
    {
        int s = tid >> 3, w = tid & 7;
        cp16(uX + (uint32_t)(buf * (TB*128) + s * 128 + w * 16),
             bb + (size_t)s * CONV_DIM + h * 64 + half * 32 + w * 4);
    }
    if (tid < TB) {
        cp4(uM + (uint32_t)(buf * (TB*16) + tid * 16),
            dts + (size_t)(bSEQ + t0 + tid) * HEADS + h);
    } else if (tid < 2*TB) {
        int s = tid - TB;
        cp4(uM + (uint32_t)(buf * (TB*16) + s * 16 + 4),
            dAs + (size_t)(bSEQ + t0 + s) * HEADS + h);
    }
}

__global__ __launch_bounds__(128, 2)
void scan_kernel(const float* __restrict__ xbc,
                 const float* __restrict__ dts,
                 const float* __restrict__ dAs,
                 const float* __restrict__ Dv,
                 float* __restrict__ y)
{
    const int bi   = blockIdx.x;
    const int half = bi & 1;
    const int h    = (bi >> 1) & 63;
    const int b    = bi >> 7;
    const int tid  = threadIdx.x;
    const int pl   = tid >> 2;
    const int nc   = tid & 3;

    __shared__ __align__(16) float sBC[2][TB][256];
    __shared__ __align__(16) float sx [2][TB][32];
    __shared__ __align__(16) float sMeta[2][TB][4];
    __shared__ __align__(16) unsigned long long sAcc[TB][32][4];

    const uint32_t uBC = s2u(sBC);
    const uint32_t uX  = s2u(sx);
    const uint32_t uM  = s2u(sMeta);

    unsigned long long st[16];
#pragma unroll
    for (int j = 0; j < 16; j++) st[j] = 0ull;

    const float Dh = Dv[h];
    const int bSEQ = b * SEQ;
    const float* base0 = xbc + (size_t)bSEQ * CONV_DIM;
    float* ybase = y + (size_t)bSEQ * INTER + h * 64 + half * 32;

    scan_load_block(uBC, uX, uM, base0, dts, dAs, bSEQ, h, half, 0, 0, tid);
    asm volatile("cp.async.commit_group;");

    for (int blk = 0; blk < NBLK; blk++) {
        const int buf = blk & 1;
        asm volatile("cp.async.wait_group 0;" ::: "memory");
        __syncthreads();

        if (blk + 1 < NBLK) {
            scan_load_block(uBC, uX, uM, base0, dts, dAs, bSEQ, h, half,
                            blk + 1, buf ^ 1, tid);
            asm volatile("cp.async.commit_group;");
        }

#pragma unroll
        for (int s = 0; s < TB; s++) {
            const float dt  = sMeta[buf][s][0];
            const float dA  = sMeta[buf][s][1];
            const float xp  = sx[buf][s][pl];
            const float dtx = dt * xp;
            const unsigned long long dA2  = pk2(dA, dA);
            const unsigned long long dtx2 = pk2(dtx, dtx);

            const char* rowB = (const char*)&sBC[buf][s][0];
            const char* rowC = rowB + 512;

            unsigned long long a0 = 0ull, a1 = 0ull, a2 = 0ull, a3 = 0ull;
#pragma unroll
            for (int q = 0; q < 8; q += 2) {
                const uint32_t o0 = (uint32_t)((q * 4 + nc) * 16);
                const uint32_t o1 = (uint32_t)(((q + 1) * 4 + nc) * 16);
                ulonglong2 bq0 = *(const ulonglong2*)(rowB + o0);
                ulonglong2 cq0 = *(const ulonglong2*)(rowC + o0);
                ulonglong2 bq1 = *(const ulonglong2*)(rowB + o1);
                ulonglong2 cq1 = *(const ulonglong2*)(rowC + o1);
                st[2*q]   = fma2_(st[2*q],   dA2, mul2_(dtx2, bq0.x));
                a0 = fma2_(cq0.x, st[2*q],   a0);
                st[2*q+1] = fma2_(st[2*q+1], dA2, mul2_(dtx2, bq0.y));
                a1 = fma2_(cq0.y, st[2*q+1], a1);
                st[2*q+2] = fma2_(st[2*q+2], dA2, mul2_(dtx2, bq1.x));
                a2 = fma2_(cq1.x, st[2*q+2], a2);
                st[2*q+3] = fma2_(st[2*q+3], dA2, mul2_(dtx2, bq1.y));
                a3 = fma2_(cq1.y, st[2*q+3], a3);
            }
            a0 = add2_(a0, a1);
            a2 = add2_(a2, a3);
            sAcc[s][pl][nc] = add2_(a0, a2);
        }
        __syncthreads();

        const int t0 = blk * TB;
#pragma unroll
        for (int i = 0; i < 4; i++) {
            int idx = tid + i * 128;
            int s  = idx >> 5;
            int pp = idx & 31;
            ulonglong2 v0 = *(const ulonglong2*)&sAcc[s][pp][0];
            ulonglong2 v1 = *(const ulonglong2*)&sAcc[s][pp][2];
            unsigned long long t = add2_(add2_(v0.x, v0.y), add2_(v1.x, v1.y));
            float f0, f1;
            asm("mov.b64 {%0,%1}, %2;" : "=f"(f0), "=f"(f1) : "l"(t));
            float xp = sx[buf][s][pp];
            ybase[(size_t)(t0 + s) * INTER + pp] = f0 + f1 + Dh * xp;
        }
    }
}

// ---------------- RMS norm + SiLU gate + fp16 hi/lo split (vectorized) ------
__global__ void norm_gate_kernel(const float* __restrict__ y,
                                 const float* __restrict__ proj,
                                 const float* __restrict__ norm_w,
                                 __half* __restrict__ Yh,
                                 __half* __restrict__ Yl)
{
    const int row = blockIdx.x;
    const int tid = threadIdx.x;
    __shared__ float red[8];
    __shared__ float s_scale;

    const float4* yrow = (const float4*)(y + (size_t)row * INTER);

    float s = 0.f;
#pragma unroll
    for (int i = 0; i < 4; i++) {
        float4 v = yrow[tid + i * 256];
        s += v.x * v.x + v.y * v.y + v.z * v.z + v.w * v.w;
    }
#pragma unroll
    for (int o = 16; o > 0; o >>= 1) s += __shfl_xor_sync(0xffffffffu, s, o);
    if ((tid & 31) == 0) red[tid >> 5] = s;
    __syncthreads();
    if (tid < 32) {
        float tot = (tid < 8) ? red[tid] : 0.f;
#pragma unroll
        for (int o = 4; o > 0; o >>= 1) tot += __shfl_xor_sync(0xffffffffu, tot, o);
        if (tid == 0) s_scale = rsqrtf(tot / (float)INTER + EPS);
    }
    __syncthreads();
    const float scale = s_scale;

    const float* prow = proj + (size_t)row * PROJ_DIM;
    __half2* Yh2 = (__half2*)(Yh + (size_t)row * INTER);
    __half2* Yl2 = (__half2*)(Yl + (size_t)row * INTER);

#pragma unroll
    for (int i = 0; i < 4; i++) {
        int i4 = tid + i * 256;
        float4 v = yrow[i4];
        float4 z = *(const float4*)(prow + i4 * 4);
        float4 w = *(const float4*)(norm_w + i4 * 4);
        float r0 = v.x * scale * w.x * (z.x / (1.f + __expf(-z.x)));
        float r1 = v.y * scale * w.y * (z.y / (1.f + __expf(-z.y)));
        float r2 = v.z * scale * w.z * (z.z / (1.f + __expf(-z.z)));
        float r3 = v.w * scale * w.w * (z.w / (1.f + __expf(-z.w)));
        __half h0 = __float2half(r0), h1 = __float2half(r1),
               h2 = __float2half(r2), h3 = __float2half(r3);
        __half l0 = __float2half(r0 - __half2float(h0));
        __half l1 = __float2half(r1 - __half2float(h1));
        __half l2 = __float2half(r2 - __half2float(h2));
        __half l3 = __float2half(r3 - __half2float(h3));
        Yh2[i4 * 2 + 0] = __halves2half2(h0, h1);
        Yh2[i4 * 2 + 1] = __halves2half2(h2, h3);
        Yl2[i4 * 2 + 0] = __halves2half2(l0, l1);
        Yl2[i4 * 2 + 1] = __halves2half2(l2, l3);
    }
}

// ---------------- launch ----------------
extern "C" void kernel_launch(void* const* d_in, const int* in_sizes, int n_in,
                              void* d_out, int out_size)
{
    const float* hidden    = (const float*)d_in[0];
    const float* in_proj_w = (const float*)d_in[1];
    const float* conv_w    = (const float*)d_in[2];
    const float* conv_b    = (const float*)d_in[3];
    const float* A_log     = (const float*)d_in[4];
    const float* Dv        = (const float*)d_in[5];
    const float* dt_bias   = (const float*)d_in[6];
    const float* norm_w    = (const float*)d_in[7];
    const float* out_proj_w= (const float*)d_in[8];
    float* out = (float*)d_out;

    float *p_proj, *p_xbc, *p_dt, *p_dA, *p_y;
    __half *p_Ah, *p_Al, *p_B1, *p_B2, *p_Yh, *p_Yl;
    cudaGetSymbolAddress((void**)&p_proj, g_proj);
    cudaGetSymbolAddress((void**)&p_xbc,  g_xbc);
    cudaGetSymbolAddress((void**)&p_dt,   g_dt);
    cudaGetSymbolAddress((void**)&p_dA,   g_dA);
    cudaGetSymbolAddress((void**)&p_y,    g_y);
    cudaGetSymbolAddress((void**)&p_Ah,   g_Ah);
    cudaGetSymbolAddress((void**)&p_Al,   g_Al);
    cudaGetSymbolAddress((void**)&p_B1,   g_B1);
    cudaGetSymbolAddress((void**)&p_B2,   g_B2);
    cudaGetSymbolAddress((void**)&p_Yh,   g_Yh);
    cudaGetSymbolAddress((void**)&p_Yl,   g_Yl);

    cudaFuncSetAttribute(gemm2p_kernel, cudaFuncAttributeMaxDynamicSharedMemorySize, GSMEM);

    // conversions
    {
        size_t n4 = (size_t)ROWS * HID / 4;
        split_kernel<<<(unsigned)((n4 + 255) / 256), 256>>>(hidden, p_Ah, p_Al, n4);
    }
    {
        dim3 grid(NPAD1 / 32, HID / 32);
        splitT_kernel<<<grid, dim3(32, 8)>>>(in_proj_w, p_B1, HID, PROJ_DIM);
    }
    {
        dim3 grid(NPAD2 / 32, INTER / 32);
        splitT_kernel<<<grid, dim3(32, 8)>>>(out_proj_w, p_B2, INTER, HID);
    }

    // GEMM1: proj = hidden @ in_proj_w * mup
    {
        dim3 grid(NPAD1 / 128, ROWS / 128);
        gemm2p_kernel<<<grid, 128, GSMEM>>>(p_Ah, p_Al, p_B1, p_proj,
                                            HID, PROJ_DIM, 1);
    }

    // fused conv + silu + dt/dA
    {
        dim3 grid((FCOLS + 127) / 128, BATCH * (SEQ / T_CHUNK));
        conv_silu_dt_kernel<<<grid, 128>>>(p_proj, conv_w, conv_b,
                                           dt_bias, A_log,
                                           p_xbc, p_dt, p_dA);
    }

    // scan (round-15, race-free)
    scan_kernel<<<BATCH * HEADS * 2, 128>>>(p_xbc, p_dt, p_dA, Dv, p_y);

    // norm + gate + split (vectorized)
    norm_gate_kernel<<<ROWS, 256>>>(p_y, p_proj, norm_w, p_Yh, p_Yl);

    // GEMM2: out = gated @ out_proj_w
    {
        dim3 grid(NPAD2 / 128, ROWS / 128);
        gemm2p_kernel<<<grid, 128, GSMEM>>>(p_Yh, p_Yl, p_B2, out,
                                            INTER, HID, 0);
    }
    (void)in_sizes; (void)n_in; (void)out_size;
}